// round 15
// baseline (speedup 1.0000x reference)
#include <cuda_runtime.h>
#include <cuda_fp16.h>
#include <cstdint>
#include <cstddef>

// ---------------- problem constants ----------------
#define N_TOK  131072
#define DMODEL 512
#define NHEADS 8
#define HDIM   64
#define SBLK   256
#define TD     1536   // 3*DMODEL
#define DFFN   1024

// ---------------- device scratch ----------------
__device__ __half g_xh  [(size_t)N_TOK * DMODEL];
__device__ __half g_qkv [(size_t)N_TOK * TD];
__device__ __half g_ctx [(size_t)N_TOK * DMODEL];
__device__ __half g_hh  [(size_t)N_TOK * DMODEL];
__device__ __half g_ff  [(size_t)N_TOK * DFFN];
__device__ __half g_t16 [(size_t)N_TOK * DMODEL];
__device__ __half g_w1  [TD     * DMODEL];
__device__ __half g_w2  [DMODEL * DMODEL];
__device__ __half g_w3  [DFFN   * DMODEL];
__device__ __half g_w4  [DMODEL * DFFN];

// ---------------- helpers ----------------
__device__ __forceinline__ uint32_t pack2(float a, float b) {
    __half2 h = __floats2half2_rn(a, b);
    return *reinterpret_cast<uint32_t*>(&h);
}
__device__ __forceinline__ void mma16816(float* c, const uint32_t* a, uint32_t b0, uint32_t b1) {
    asm volatile(
        "mma.sync.aligned.m16n8k16.row.col.f32.f16.f16.f32 "
        "{%0,%1,%2,%3}, {%4,%5,%6,%7}, {%8,%9}, {%0,%1,%2,%3};\n"
        : "+f"(c[0]), "+f"(c[1]), "+f"(c[2]), "+f"(c[3])
        : "r"(a[0]), "r"(a[1]), "r"(a[2]), "r"(a[3]), "r"(b0), "r"(b1));
}
__device__ __forceinline__ void ldsm4(uint32_t* r, uint32_t addr) {
    asm volatile("ldmatrix.sync.aligned.m8n8.x4.shared.b16 {%0,%1,%2,%3}, [%4];"
        : "=r"(r[0]), "=r"(r[1]), "=r"(r[2]), "=r"(r[3]) : "r"(addr));
}
__device__ __forceinline__ void ldsm4t(uint32_t* r, uint32_t addr) {
    asm volatile("ldmatrix.sync.aligned.m8n8.x4.trans.shared.b16 {%0,%1,%2,%3}, [%4];"
        : "=r"(r[0]), "=r"(r[1]), "=r"(r[2]), "=r"(r[3]) : "r"(addr));
}
__device__ __forceinline__ void cp16(uint32_t dst, const void* src) {
    asm volatile("cp.async.cg.shared.global [%0], [%1], 16;" :: "r"(dst), "l"(src));
}
__device__ __forceinline__ float gelu_exact(float v) {
    return 0.5f * v * (1.0f + erff(v * 0.7071067811865476f));
}

// ---------------- fp32 -> fp16 converts: x + all 4 weights, one launch ----------------
__global__ void convall_kernel(const float* __restrict__ x,
                               const float* __restrict__ wq, const float* __restrict__ wo,
                               const float* __restrict__ wa, const float* __restrict__ wb,
                               __half* __restrict__ dx,
                               __half* __restrict__ d1, __half* __restrict__ d2,
                               __half* __restrict__ d3, __half* __restrict__ d4) {
    size_t i = ((size_t)blockIdx.x * blockDim.x + threadIdx.x) * 4;
    const float* src; __half* dst; size_t off;
    if      (i < 67108864)             { src = x;  dst = dx; off = i; }
    else if (i < 67108864 + 786432)    { src = wq; dst = d1; off = i - 67108864; }
    else if (i < 67108864 + 1048576)   { src = wo; dst = d2; off = i - 67108864 - 786432; }
    else if (i < 67108864 + 1572864)   { src = wa; dst = d3; off = i - 67108864 - 1048576; }
    else                               { src = wb; dst = d4; off = i - 67108864 - 1572864; }
    float4 v = *(const float4*)(src + off);
    __half2* o = (__half2*)(dst + off);
    o[0] = __floats2half2_rn(v.x, v.y);
    o[1] = __floats2half2_rn(v.z, v.w);
}

// ---------------- pipelined GEMM with warp-phase kstep rotation (R12, unchanged) ----------------
#define GS      3
#define GSTG_B  36864
#define GSMEM   (GS * GSTG_B)

template<int EPI>
__global__ __launch_bounds__(256, 2) void gemm_kernel(
    const __half* __restrict__ A, const __half* __restrict__ B,
    const float* __restrict__ bias, __half* __restrict__ Cout,
    int M, int Nn, int K)
{
    extern __shared__ __half gsm[];
    const uint32_t smem_u = (uint32_t)__cvta_generic_to_shared(gsm);

    const int tid  = threadIdx.x;
    const int lane = tid & 31, warp = tid >> 5;
    const int wm = warp & 3;
    const int wn = warp >> 2;
    const int lr = lane >> 2, lc = lane & 3;
    const int bm = blockIdx.y * 128, bn = blockIdx.x * 128;
    const int krot = warp & 3;

    float acc[2][8][4];
#pragma unroll
    for (int mi = 0; mi < 2; mi++)
#pragma unroll
        for (int nj = 0; nj < 8; nj++)
#pragma unroll
            for (int e = 0; e < 4; e++) acc[mi][nj][e] = 0.0f;

    const int r0 = tid >> 3;
    const int cc = tid & 7;
    const __half* Ag = A + (size_t)(bm + r0) * K + cc * 8;
    const __half* Bg = B + (size_t)(bn + r0) * K + cc * 8;
    const uint32_t stA = smem_u + r0 * 144 + cc * 16;
    const uint32_t stB = stA + 18432;

    const uint32_t aBase = smem_u +
        (((wm * 32 + (lane & 15)) * 72 + ((lane >> 4) << 3)) << 1);
    const uint32_t bBase = smem_u + 18432 +
        (((wn * 64 + ((lane & 16) >> 1) + (lane & 7)) * 72 + (lane & 8)) << 1);

    const int niter = K >> 6;

#define LOAD_STAGE(s, k0) do {                                    \
    const uint32_t off = (uint32_t)(s) * GSTG_B;                  \
    _Pragma("unroll")                                             \
    for (int j = 0; j < 4; j++)                                   \
        cp16(stA + off + j * 4608, Ag + (k0) + (size_t)(32 * j) * K); \
    _Pragma("unroll")                                             \
    for (int j = 0; j < 4; j++)                                   \
        cp16(stB + off + j * 4608, Bg + (k0) + (size_t)(32 * j) * K); \
    } while (0)

    LOAD_STAGE(0, 0);  asm volatile("cp.async.commit_group;");
    LOAD_STAGE(1, 64); asm volatile("cp.async.commit_group;");

    for (int d = 0; d < niter; d++) {
        asm volatile("cp.async.wait_group 1;");
        __syncthreads();
        if (d + 2 < niter) LOAD_STAGE((d + 2) % GS, (d + 2) << 6);
        asm volatile("cp.async.commit_group;");

        const uint32_t soff = (uint32_t)(d % GS) * GSTG_B;
#pragma unroll
        for (int k0 = 0; k0 < 4; k0++) {
            const int ks = (k0 + krot) & 3;
            uint32_t af[2][4];
            ldsm4(af[0], aBase + soff + ks * 32);
            ldsm4(af[1], aBase + soff + ks * 32 + 16 * 144);
#pragma unroll
            for (int njp = 0; njp < 4; njp++) {
                uint32_t bf[4];
                ldsm4(bf, bBase + soff + ks * 32 + njp * 16 * 144);
                mma16816(acc[0][2 * njp],     af[0], bf[0], bf[1]);
                mma16816(acc[1][2 * njp],     af[1], bf[0], bf[1]);
                mma16816(acc[0][2 * njp + 1], af[0], bf[2], bf[3]);
                mma16816(acc[1][2 * njp + 1], af[1], bf[2], bf[3]);
            }
        }
    }
#undef LOAD_STAGE

    __syncthreads();

#pragma unroll
    for (int mi = 0; mi < 2; mi++) {
#pragma unroll
        for (int nj = 0; nj < 8; nj++) {
            int gr = bm + wm * 32 + mi * 16 + lr;
            int gc = bn + wn * 64 + nj * 8 + lc * 2;
            float bb0 = bias[gc], bb1 = bias[gc + 1];
            float v00 = acc[mi][nj][0] + bb0;
            float v01 = acc[mi][nj][1] + bb1;
            float v10 = acc[mi][nj][2] + bb0;
            float v11 = acc[mi][nj][3] + bb1;
            if (EPI == 2) {
                v00 = gelu_exact(v00); v01 = gelu_exact(v01);
                v10 = gelu_exact(v10); v11 = gelu_exact(v11);
            }
            *(uint32_t*)&Cout[(size_t)gr * Nn + gc]       = pack2(v00, v01);
            *(uint32_t*)&Cout[(size_t)(gr + 8) * Nn + gc] = pack2(v10, v11);
        }
    }
}

// ---------------- attention: interleaved S-MMA / exp / PV-MMA (clean A/B of R13 change) ----------------
#define ATTN_SMEM_HALVES (3 * 256 * 72)

__global__ __launch_bounds__(256, 2) void attn_kernel(
    const __half* __restrict__ qkv, __half* __restrict__ ctx)
{
    extern __shared__ __half sm[];
    __half* sQ = sm;                   // [256][72] token-major
    __half* sK = sm + 256 * 72;
    __half* sV = sm + 2 * 256 * 72;

    const int tid  = threadIdx.x;
    const int lane = tid & 31, warp = tid >> 5;
    const int lr = lane >> 2, lc = lane & 3;
    const int b = blockIdx.x >> 3, h = blockIdx.x & 7;
    const __half* base = qkv + (size_t)b * SBLK * TD;

    const uint32_t sQ_u = (uint32_t)__cvta_generic_to_shared(sQ);
    const uint32_t sK_u = (uint32_t)__cvta_generic_to_shared(sK);
    const uint32_t sV_u = (uint32_t)__cvta_generic_to_shared(sV);

    for (int idx = tid; idx < 256 * 16; idx += 256) {
        int t = idx >> 4, d4 = (idx & 15) * 4;
        const __half* p = base + (size_t)t * TD + h * HDIM + d4;
        uint2 vq = *(const uint2*)(p);
        uint2 vk = *(const uint2*)(p + DMODEL);
        uint2 vv = *(const uint2*)(p + 2 * DMODEL);
        *(uint2*)&sQ[t * 72 + d4] = vq;
        *(uint2*)&sK[t * 72 + d4] = vk;
        *(uint2*)&sV[t * 72 + d4] = vv;
    }
    __syncthreads();

    const uint32_t qBase = sQ_u +
        (((lane & 15) * 72 + ((lane >> 4) << 3)) << 1);
    const uint32_t kBase = sK_u +
        (((((lane & 16) >> 1) + (lane & 7)) * 72 + (lane & 8)) << 1);
    const uint32_t vBase = sV_u +
        ((((lane & 8) + (lane & 7)) * 72 + ((lane & 16) >> 1)) << 1);

#pragma unroll 1
    for (int mh = 0; mh < 2; mh++) {
        const int mbase = mh * 128 + warp * 16;

        uint32_t qf[4][4];
#pragma unroll
        for (int ks = 0; ks < 4; ks++)
            ldsm4(qf[ks], qBase + mbase * 144 + ks * 32);

        float o[8][4];
#pragma unroll
        for (int dj = 0; dj < 8; dj++)
#pragma unroll
            for (int e = 0; e < 4; e++) o[dj][e] = 0.0f;
        float rs0 = 0.f, rs1 = 0.f;

#pragma unroll
        for (int kt = 0; kt < 4; kt++) {
#pragma unroll
            for (int njp = 0; njp < 4; njp++) {
                // ---- S for this 16-token column pair ----
                float s0[4] = {0.f, 0.f, 0.f, 0.f};
                float s1[4] = {0.f, 0.f, 0.f, 0.f};
#pragma unroll
                for (int ks = 0; ks < 4; ks++) {
                    uint32_t bf[4];
                    ldsm4(bf, kBase + (((kt * 64 + njp * 16) * 72 + ks * 16) << 1));
                    mma16816(s0, qf[ks], bf[0], bf[1]);
                    mma16816(s1, qf[ks], bf[2], bf[3]);
                }

                // ---- exp + pack ----
                float e00 = __expf(s0[0] * 0.125f);
                float e01 = __expf(s0[1] * 0.125f);
                float e02 = __expf(s0[2] * 0.125f);
                float e03 = __expf(s0[3] * 0.125f);
                float e10 = __expf(s1[0] * 0.125f);
                float e11 = __expf(s1[1] * 0.125f);
                float e12 = __expf(s1[2] * 0.125f);
                float e13 = __expf(s1[3] * 0.125f);
                rs0 += e00 + e01 + e10 + e11;
                rs1 += e02 + e03 + e12 + e13;
                uint32_t pa[4];
                pa[0] = pack2(e00, e01);
                pa[1] = pack2(e02, e03);
                pa[2] = pack2(e10, e11);
                pa[3] = pack2(e12, e13);

                // ---- O += P(:, these 16 tokens) * V(these 16 tokens, :) ----
#pragma unroll
                for (int djp = 0; djp < 4; djp++) {
                    uint32_t bf[4];
                    ldsm4t(bf, vBase + (((kt * 64 + njp * 16) * 72 + djp * 16) << 1));
                    mma16816(o[2 * djp],     pa, bf[0], bf[1]);
                    mma16816(o[2 * djp + 1], pa, bf[2], bf[3]);
                }
            }
        }

        rs0 += __shfl_xor_sync(0xffffffffu, rs0, 1);
        rs0 += __shfl_xor_sync(0xffffffffu, rs0, 2);
        rs1 += __shfl_xor_sync(0xffffffffu, rs1, 1);
        rs1 += __shfl_xor_sync(0xffffffffu, rs1, 2);

        const float i0 = 1.0f / rs0;
        const float i1 = 1.0f / rs1;
#pragma unroll
        for (int dj = 0; dj < 8; dj++) {
            int gr = b * SBLK + mbase + lr;
            int gc = h * HDIM + dj * 8 + lc * 2;
            *(uint32_t*)&ctx[(size_t)gr * DMODEL + gc] =
                pack2(o[dj][0] * i0, o[dj][1] * i0);
            *(uint32_t*)&ctx[(size_t)(gr + 8) * DMODEL + gc] =
                pack2(o[dj][2] * i1, o[dj][3] * i1);
        }
    }
}

// ---------------- residual add + LayerNorm: warp per row ----------------
__global__ void add_ln1_kernel(
    const __half* __restrict__ res, const __half* __restrict__ y,
    const float* __restrict__ gam, const float* __restrict__ bet,
    __half* __restrict__ out16)
{
    const int lane = threadIdx.x & 31;
    const int row  = blockIdx.x * 8 + (threadIdx.x >> 5);
    const size_t roff = (size_t)row * DMODEL;
    const int c0 = lane * 4;

    float v[16];
#pragma unroll
    for (int i = 0; i < 4; i++) {
        uint2 rv = *(const uint2*)(res + roff + i * 128 + c0);
        uint2 yv = *(const uint2*)(y   + roff + i * 128 + c0);
        float2 a0 = __half22float2(*(__half2*)&rv.x);
        float2 a1 = __half22float2(*(__half2*)&rv.y);
        float2 f0 = __half22float2(*(__half2*)&yv.x);
        float2 f1 = __half22float2(*(__half2*)&yv.y);
        v[i*4+0] = a0.x + f0.x; v[i*4+1] = a0.y + f0.y;
        v[i*4+2] = a1.x + f1.x; v[i*4+3] = a1.y + f1.y;
    }
    float sum = 0.f, sq = 0.f;
#pragma unroll
    for (int k = 0; k < 16; k++) { sum += v[k]; sq += v[k] * v[k]; }
#pragma unroll
    for (int ofs = 16; ofs > 0; ofs >>= 1) {
        sum += __shfl_xor_sync(0xffffffffu, sum, ofs);
        sq  += __shfl_xor_sync(0xffffffffu, sq, ofs);
    }
    float mu   = sum * (1.0f / 512.0f);
    float var  = sq * (1.0f / 512.0f) - mu * mu;
    float rstd = rsqrtf(var + 1e-5f);

#pragma unroll
    for (int i = 0; i < 4; i++) {
        float4 g  = *(const float4*)(gam + i * 128 + c0);
        float4 be = *(const float4*)(bet + i * 128 + c0);
        float o0 = (v[i*4+0] - mu) * rstd * g.x + be.x;
        float o1 = (v[i*4+1] - mu) * rstd * g.y + be.y;
        float o2 = (v[i*4+2] - mu) * rstd * g.z + be.z;
        float o3 = (v[i*4+3] - mu) * rstd * g.w + be.w;
        uint2 w; w.x = pack2(o0, o1); w.y = pack2(o2, o3);
        *(uint2*)(out16 + roff + i * 128 + c0) = w;
    }
}

__global__ void add_ln2_kernel(
    const __half* __restrict__ res, const __half* __restrict__ y,
    const float* __restrict__ gam, const float* __restrict__ bet,
    float* __restrict__ out32)
{
    const int lane = threadIdx.x & 31;
    const int row  = blockIdx.x * 8 + (threadIdx.x >> 5);
    const size_t roff = (size_t)row * DMODEL;
    const int c0 = lane * 4;

    float v[16];
#pragma unroll
    for (int i = 0; i < 4; i++) {
        uint2 rv = *(const uint2*)(res + roff + i * 128 + c0);
        uint2 yv = *(const uint2*)(y   + roff + i * 128 + c0);
        float2 a0 = __half22float2(*(__half2*)&rv.x);
        float2 a1 = __half22float2(*(__half2*)&rv.y);
        float2 f0 = __half22float2(*(__half2*)&yv.x);
        float2 f1 = __half22float2(*(__half2*)&yv.y);
        v[i*4+0] = a0.x + f0.x; v[i*4+1] = a0.y + f0.y;
        v[i*4+2] = a1.x + f1.x; v[i*4+3] = a1.y + f1.y;
    }
    float sum = 0.f, sq = 0.f;
#pragma unroll
    for (int k = 0; k < 16; k++) { sum += v[k]; sq += v[k] * v[k]; }
#pragma unroll
    for (int ofs = 16; ofs > 0; ofs >>= 1) {
        sum += __shfl_xor_sync(0xffffffffu, sum, ofs);
        sq  += __shfl_xor_sync(0xffffffffu, sq, ofs);
    }
    float mu   = sum * (1.0f / 512.0f);
    float var  = sq * (1.0f / 512.0f) - mu * mu;
    float rstd = rsqrtf(var + 1e-5f);

#pragma unroll
    for (int i = 0; i < 4; i++) {
        float4 g  = *(const float4*)(gam + i * 128 + c0);
        float4 be = *(const float4*)(bet + i * 128 + c0);
        float4 w;
        w.x = (v[i*4+0] - mu) * rstd * g.x + be.x;
        w.y = (v[i*4+1] - mu) * rstd * g.y + be.y;
        w.z = (v[i*4+2] - mu) * rstd * g.z + be.z;
        w.w = (v[i*4+3] - mu) * rstd * g.w + be.w;
        *(float4*)(out32 + roff + i * 128 + c0) = w;
    }
}

// ---------------- launch ----------------
extern "C" void kernel_launch(void* const* d_in, const int* in_sizes, int n_in,
                              void* d_out, int out_size)
{
    const float* x      = (const float*)d_in[0];
    const float* w_qkv  = (const float*)d_in[1];
    const float* b_qkv  = (const float*)d_in[2];
    const float* w_out  = (const float*)d_in[3];
    const float* b_out  = (const float*)d_in[4];
    const float* w_l1   = (const float*)d_in[5];
    const float* b_l1   = (const float*)d_in[6];
    const float* w_l2   = (const float*)d_in[7];
    const float* b_l2   = (const float*)d_in[8];
    const float* ln1_g  = (const float*)d_in[9];
    const float* ln1_b  = (const float*)d_in[10];
    const float* ln2_g  = (const float*)d_in[11];
    const float* ln2_b  = (const float*)d_in[12];
    float* out = (float*)d_out;

    __half *xh, *qkv, *ctx, *hh, *ff, *t16, *w1, *w2, *w3, *w4;
    cudaGetSymbolAddress((void**)&xh,  g_xh);
    cudaGetSymbolAddress((void**)&qkv, g_qkv);
    cudaGetSymbolAddress((void**)&ctx, g_ctx);
    cudaGetSymbolAddress((void**)&hh,  g_hh);
    cudaGetSymbolAddress((void**)&ff,  g_ff);
    cudaGetSymbolAddress((void**)&t16, g_t16);
    cudaGetSymbolAddress((void**)&w1,  g_w1);
    cudaGetSymbolAddress((void**)&w2,  g_w2);
    cudaGetSymbolAddress((void**)&w3,  g_w3);
    cudaGetSymbolAddress((void**)&w4,  g_w4);

    const int attn_smem = ATTN_SMEM_HALVES * 2;   // 110592 B
    cudaFuncSetAttribute(attn_kernel, cudaFuncAttributeMaxDynamicSharedMemorySize, attn_smem);
    cudaFuncSetAttribute(gemm_kernel<0>, cudaFuncAttributeMaxDynamicSharedMemorySize, GSMEM);
    cudaFuncSetAttribute(gemm_kernel<2>, cudaFuncAttributeMaxDynamicSharedMemorySize, GSMEM);

    // converts (x + all weights, one launch)
    convall_kernel<<<(67108864 + 2097152) / 1024, 256>>>(
        x, w_qkv, w_out, w_l1, w_l2, xh, w1, w2, w3, w4);

    // 1) qkv = x @ in_proj_w^T + b
    gemm_kernel<0><<<dim3(TD / 128, N_TOK / 128), 256, GSMEM>>>(xh, w1, b_qkv, qkv, N_TOK, TD, DMODEL);

    // 2) attention
    attn_kernel<<<(N_TOK / SBLK) * NHEADS, 256, attn_smem>>>(qkv, ctx);

    // 3) attn_out = ctx @ out_w^T + b (fp16)
    gemm_kernel<0><<<dim3(DMODEL / 128, N_TOK / 128), 256, GSMEM>>>(ctx, w2, b_out, t16, N_TOK, DMODEL, DMODEL);

    // 4) hh = LN1(xh + attn_out)
    add_ln1_kernel<<<N_TOK / 8, 256>>>(xh, t16, ln1_g, ln1_b, hh);

    // 5) ff = gelu(hh @ lin1_w^T + b)
    gemm_kernel<2><<<dim3(DFFN / 128, N_TOK / 128), 256, GSMEM>>>(hh, w3, b_l1, ff, N_TOK, DFFN, DMODEL);

    // 6) f2 = ff @ lin2_w^T + b (fp16)
    gemm_kernel<0><<<dim3(DMODEL / 128, N_TOK / 128), 256, GSMEM>>>(ff, w4, b_l2, t16, N_TOK, DMODEL, DFFN);

    // 7) out = LN2(hh + f2)
    add_ln2_kernel<<<N_TOK / 8, 256>>>(hh, t16, ln2_g, ln2_b, out);
}

// round 16
// speedup vs baseline: 1.0057x; 1.0057x over previous
#include <cuda_runtime.h>
#include <cuda_fp16.h>
#include <cstdint>
#include <cstddef>

// ---------------- problem constants ----------------
#define N_TOK  131072
#define DMODEL 512
#define NHEADS 8
#define HDIM   64
#define SBLK   256
#define TD     1536   // 3*DMODEL
#define DFFN   1024

// ---------------- device scratch ----------------
__device__ __half g_xh  [(size_t)N_TOK * DMODEL];
__device__ __half g_qkv [(size_t)N_TOK * TD];
__device__ __half g_ctx [(size_t)N_TOK * DMODEL];
__device__ __half g_hh  [(size_t)N_TOK * DMODEL];
__device__ __half g_ff  [(size_t)N_TOK * DFFN];
__device__ __half g_t16 [(size_t)N_TOK * DMODEL];
__device__ __half g_w1  [TD     * DMODEL];
__device__ __half g_w2  [DMODEL * DMODEL];
__device__ __half g_w3  [DFFN   * DMODEL];
__device__ __half g_w4  [DMODEL * DFFN];

// ---------------- helpers ----------------
__device__ __forceinline__ uint32_t pack2(float a, float b) {
    __half2 h = __floats2half2_rn(a, b);
    return *reinterpret_cast<uint32_t*>(&h);
}
__device__ __forceinline__ void mma16816(float* c, const uint32_t* a, uint32_t b0, uint32_t b1) {
    asm volatile(
        "mma.sync.aligned.m16n8k16.row.col.f32.f16.f16.f32 "
        "{%0,%1,%2,%3}, {%4,%5,%6,%7}, {%8,%9}, {%0,%1,%2,%3};\n"
        : "+f"(c[0]), "+f"(c[1]), "+f"(c[2]), "+f"(c[3])
        : "r"(a[0]), "r"(a[1]), "r"(a[2]), "r"(a[3]), "r"(b0), "r"(b1));
}
__device__ __forceinline__ void ldsm4(uint32_t* r, uint32_t addr) {
    asm volatile("ldmatrix.sync.aligned.m8n8.x4.shared.b16 {%0,%1,%2,%3}, [%4];"
        : "=r"(r[0]), "=r"(r[1]), "=r"(r[2]), "=r"(r[3]) : "r"(addr));
}
__device__ __forceinline__ void ldsm4t(uint32_t* r, uint32_t addr) {
    asm volatile("ldmatrix.sync.aligned.m8n8.x4.trans.shared.b16 {%0,%1,%2,%3}, [%4];"
        : "=r"(r[0]), "=r"(r[1]), "=r"(r[2]), "=r"(r[3]) : "r"(addr));
}
__device__ __forceinline__ void cp16(uint32_t dst, const void* src) {
    asm volatile("cp.async.cg.shared.global [%0], [%1], 16;" :: "r"(dst), "l"(src));
}
__device__ __forceinline__ float gelu_exact(float v) {
    return 0.5f * v * (1.0f + erff(v * 0.7071067811865476f));
}

// ---------------- fp32 -> fp16 converts: x + all 4 weights, one launch ----------------
__global__ void convall_kernel(const float* __restrict__ x,
                               const float* __restrict__ wq, const float* __restrict__ wo,
                               const float* __restrict__ wa, const float* __restrict__ wb,
                               __half* __restrict__ dx,
                               __half* __restrict__ d1, __half* __restrict__ d2,
                               __half* __restrict__ d3, __half* __restrict__ d4) {
    size_t i = ((size_t)blockIdx.x * blockDim.x + threadIdx.x) * 4;
    const float* src; __half* dst; size_t off;
    if      (i < 67108864)             { src = x;  dst = dx; off = i; }
    else if (i < 67108864 + 786432)    { src = wq; dst = d1; off = i - 67108864; }
    else if (i < 67108864 + 1048576)   { src = wo; dst = d2; off = i - 67108864 - 786432; }
    else if (i < 67108864 + 1572864)   { src = wa; dst = d3; off = i - 67108864 - 1048576; }
    else                               { src = wb; dst = d4; off = i - 67108864 - 1572864; }
    float4 v = *(const float4*)(src + off);
    __half2* o = (__half2*)(dst + off);
    o[0] = __floats2half2_rn(v.x, v.y);
    o[1] = __floats2half2_rn(v.z, v.w);
}

// ---------------- pipelined GEMM: kstep rotation + explicit fragment double buffering ----------------
// A fragments double-buffered across ksteps, B fragments double-buffered across
// njp steps: every ldmatrix issues >=4 MMAs before its consumer, hiding LDSM
// latency that ptxas cannot hoist at the 128-reg cap.
#define GS      3
#define GSTG_B  36864
#define GSMEM   (GS * GSTG_B)

template<int EPI>
__global__ __launch_bounds__(256, 2) void gemm_kernel(
    const __half* __restrict__ A, const __half* __restrict__ B,
    const float* __restrict__ bias, __half* __restrict__ Cout,
    int M, int Nn, int K)
{
    extern __shared__ __half gsm[];
    const uint32_t smem_u = (uint32_t)__cvta_generic_to_shared(gsm);

    const int tid  = threadIdx.x;
    const int lane = tid & 31, warp = tid >> 5;
    const int wm = warp & 3;
    const int wn = warp >> 2;
    const int lr = lane >> 2, lc = lane & 3;
    const int bm = blockIdx.y * 128, bn = blockIdx.x * 128;
    const int krot = warp & 3;

    float acc[2][8][4];
#pragma unroll
    for (int mi = 0; mi < 2; mi++)
#pragma unroll
        for (int nj = 0; nj < 8; nj++)
#pragma unroll
            for (int e = 0; e < 4; e++) acc[mi][nj][e] = 0.0f;

    const int r0 = tid >> 3;
    const int cc = tid & 7;
    const __half* Ag = A + (size_t)(bm + r0) * K + cc * 8;
    const __half* Bg = B + (size_t)(bn + r0) * K + cc * 8;
    const uint32_t stA = smem_u + r0 * 144 + cc * 16;
    const uint32_t stB = stA + 18432;

    const uint32_t aBase = smem_u +
        (((wm * 32 + (lane & 15)) * 72 + ((lane >> 4) << 3)) << 1);
    const uint32_t bBase = smem_u + 18432 +
        (((wn * 64 + ((lane & 16) >> 1) + (lane & 7)) * 72 + (lane & 8)) << 1);

    const int niter = K >> 6;

#define LOAD_STAGE(s, k0) do {                                    \
    const uint32_t off = (uint32_t)(s) * GSTG_B;                  \
    _Pragma("unroll")                                             \
    for (int j = 0; j < 4; j++)                                   \
        cp16(stA + off + j * 4608, Ag + (k0) + (size_t)(32 * j) * K); \
    _Pragma("unroll")                                             \
    for (int j = 0; j < 4; j++)                                   \
        cp16(stB + off + j * 4608, Bg + (k0) + (size_t)(32 * j) * K); \
    } while (0)

    LOAD_STAGE(0, 0);  asm volatile("cp.async.commit_group;");
    LOAD_STAGE(1, 64); asm volatile("cp.async.commit_group;");

    for (int d = 0; d < niter; d++) {
        asm volatile("cp.async.wait_group 1;");
        __syncthreads();
        if (d + 2 < niter) LOAD_STAGE((d + 2) % GS, (d + 2) << 6);
        asm volatile("cp.async.commit_group;");

        const uint32_t soff = (uint32_t)(d % GS) * GSTG_B;

        uint32_t af[2][2][4];   // [buf][mi][frag] - A, double-buffered across ksteps
        uint32_t bf[2][4];      // [buf][frag]     - B, double-buffered across njp

        // preload: A frags of first kstep, B frag of first njp
        ldsm4(af[0][0], aBase + soff + krot * 32);
        ldsm4(af[0][1], aBase + soff + krot * 32 + 16 * 144);
        ldsm4(bf[0],    bBase + soff + krot * 32);

#pragma unroll
        for (int k0 = 0; k0 < 4; k0++) {
            const int ks  = (k0 + krot) & 3;
            const int ksn = (k0 + 1 + krot) & 3;
            const int ab  = k0 & 1;
            // prefetch next kstep's A fragments
            if (k0 < 3) {
                ldsm4(af[ab ^ 1][0], aBase + soff + ksn * 32);
                ldsm4(af[ab ^ 1][1], aBase + soff + ksn * 32 + 16 * 144);
            }
#pragma unroll
            for (int njp = 0; njp < 4; njp++) {
                const int bb = njp & 1;
                // prefetch next B fragment (next njp, or njp=0 of next kstep)
                if (njp < 3)
                    ldsm4(bf[bb ^ 1], bBase + soff + ks * 32 + (njp + 1) * 16 * 144);
                else if (k0 < 3)
                    ldsm4(bf[bb ^ 1], bBase + soff + ksn * 32);
                mma16816(acc[0][2 * njp],     af[ab][0], bf[bb][0], bf[bb][1]);
                mma16816(acc[1][2 * njp],     af[ab][1], bf[bb][0], bf[bb][1]);
                mma16816(acc[0][2 * njp + 1], af[ab][0], bf[bb][2], bf[bb][3]);
                mma16816(acc[1][2 * njp + 1], af[ab][1], bf[bb][2], bf[bb][3]);
            }
        }
    }
#undef LOAD_STAGE

    __syncthreads();

#pragma unroll
    for (int mi = 0; mi < 2; mi++) {
#pragma unroll
        for (int nj = 0; nj < 8; nj++) {
            int gr = bm + wm * 32 + mi * 16 + lr;
            int gc = bn + wn * 64 + nj * 8 + lc * 2;
            float bb0 = bias[gc], bb1 = bias[gc + 1];
            float v00 = acc[mi][nj][0] + bb0;
            float v01 = acc[mi][nj][1] + bb1;
            float v10 = acc[mi][nj][2] + bb0;
            float v11 = acc[mi][nj][3] + bb1;
            if (EPI == 2) {
                v00 = gelu_exact(v00); v01 = gelu_exact(v01);
                v10 = gelu_exact(v10); v11 = gelu_exact(v11);
            }
            *(uint32_t*)&Cout[(size_t)gr * Nn + gc]       = pack2(v00, v01);
            *(uint32_t*)&Cout[(size_t)(gr + 8) * Nn + gc] = pack2(v10, v11);
        }
    }
}

// ---------------- attention: Q/K/V staged in smem; ldsm everywhere (R12-proven) ----------------
#define ATTN_SMEM_HALVES (3 * 256 * 72)

__global__ __launch_bounds__(256, 2) void attn_kernel(
    const __half* __restrict__ qkv, __half* __restrict__ ctx)
{
    extern __shared__ __half sm[];
    __half* sQ = sm;                   // [256][72] token-major
    __half* sK = sm + 256 * 72;
    __half* sV = sm + 2 * 256 * 72;

    const int tid  = threadIdx.x;
    const int lane = tid & 31, warp = tid >> 5;
    const int lr = lane >> 2, lc = lane & 3;
    const int b = blockIdx.x >> 3, h = blockIdx.x & 7;
    const __half* base = qkv + (size_t)b * SBLK * TD;

    const uint32_t sQ_u = (uint32_t)__cvta_generic_to_shared(sQ);
    const uint32_t sK_u = (uint32_t)__cvta_generic_to_shared(sK);
    const uint32_t sV_u = (uint32_t)__cvta_generic_to_shared(sV);

    for (int idx = tid; idx < 256 * 16; idx += 256) {
        int t = idx >> 4, d4 = (idx & 15) * 4;
        const __half* p = base + (size_t)t * TD + h * HDIM + d4;
        uint2 vq = *(const uint2*)(p);
        uint2 vk = *(const uint2*)(p + DMODEL);
        uint2 vv = *(const uint2*)(p + 2 * DMODEL);
        *(uint2*)&sQ[t * 72 + d4] = vq;
        *(uint2*)&sK[t * 72 + d4] = vk;
        *(uint2*)&sV[t * 72 + d4] = vv;
    }
    __syncthreads();

    const uint32_t qBase = sQ_u +
        (((lane & 15) * 72 + ((lane >> 4) << 3)) << 1);
    const uint32_t kBase = sK_u +
        (((((lane & 16) >> 1) + (lane & 7)) * 72 + (lane & 8)) << 1);
    const uint32_t vBase = sV_u +
        ((((lane & 8) + (lane & 7)) * 72 + ((lane & 16) >> 1)) << 1);

#pragma unroll 1
    for (int mh = 0; mh < 2; mh++) {
        const int mbase = mh * 128 + warp * 16;

        uint32_t qf[4][4];
#pragma unroll
        for (int ks = 0; ks < 4; ks++)
            ldsm4(qf[ks], qBase + mbase * 144 + ks * 32);

        float o[8][4];
#pragma unroll
        for (int dj = 0; dj < 8; dj++)
#pragma unroll
            for (int e = 0; e < 4; e++) o[dj][e] = 0.0f;
        float rs0 = 0.f, rs1 = 0.f;

#pragma unroll
        for (int kt = 0; kt < 4; kt++) {
            float s[8][4];
#pragma unroll
            for (int nj = 0; nj < 8; nj++)
#pragma unroll
                for (int e = 0; e < 4; e++) s[nj][e] = 0.0f;

#pragma unroll
            for (int ks = 0; ks < 4; ks++) {
#pragma unroll
                for (int njp = 0; njp < 4; njp++) {
                    uint32_t bf[4];
                    ldsm4(bf, kBase + (((kt * 64 + njp * 16) * 72 + ks * 16) << 1));
                    mma16816(s[2 * njp],     qf[ks], bf[0], bf[1]);
                    mma16816(s[2 * njp + 1], qf[ks], bf[2], bf[3]);
                }
            }

            uint32_t pa[4][4];
#pragma unroll
            for (int nj = 0; nj < 8; nj++) {
                float e0 = __expf(s[nj][0] * 0.125f);
                float e1 = __expf(s[nj][1] * 0.125f);
                float e2 = __expf(s[nj][2] * 0.125f);
                float e3 = __expf(s[nj][3] * 0.125f);
                rs0 += e0 + e1;
                rs1 += e2 + e3;
                pa[nj >> 1][(nj & 1) * 2 + 0] = pack2(e0, e1);
                pa[nj >> 1][(nj & 1) * 2 + 1] = pack2(e2, e3);
            }

#pragma unroll
            for (int ks2 = 0; ks2 < 4; ks2++) {
#pragma unroll
                for (int djp = 0; djp < 4; djp++) {
                    uint32_t bf[4];
                    ldsm4t(bf, vBase + (((kt * 64 + ks2 * 16) * 72 + djp * 16) << 1));
                    mma16816(o[2 * djp],     pa[ks2], bf[0], bf[1]);
                    mma16816(o[2 * djp + 1], pa[ks2], bf[2], bf[3]);
                }
            }
        }

        rs0 += __shfl_xor_sync(0xffffffffu, rs0, 1);
        rs0 += __shfl_xor_sync(0xffffffffu, rs0, 2);
        rs1 += __shfl_xor_sync(0xffffffffu, rs1, 1);
        rs1 += __shfl_xor_sync(0xffffffffu, rs1, 2);

        const float i0 = 1.0f / rs0;
        const float i1 = 1.0f / rs1;
#pragma unroll
        for (int dj = 0; dj < 8; dj++) {
            int gr = b * SBLK + mbase + lr;
            int gc = h * HDIM + dj * 8 + lc * 2;
            *(uint32_t*)&ctx[(size_t)gr * DMODEL + gc] =
                pack2(o[dj][0] * i0, o[dj][1] * i0);
            *(uint32_t*)&ctx[(size_t)(gr + 8) * DMODEL + gc] =
                pack2(o[dj][2] * i1, o[dj][3] * i1);
        }
    }
}

// ---------------- residual add + LayerNorm: warp per row ----------------
__global__ void add_ln1_kernel(
    const __half* __restrict__ res, const __half* __restrict__ y,
    const float* __restrict__ gam, const float* __restrict__ bet,
    __half* __restrict__ out16)
{
    const int lane = threadIdx.x & 31;
    const int row  = blockIdx.x * 8 + (threadIdx.x >> 5);
    const size_t roff = (size_t)row * DMODEL;
    const int c0 = lane * 4;

    float v[16];
#pragma unroll
    for (int i = 0; i < 4; i++) {
        uint2 rv = *(const uint2*)(res + roff + i * 128 + c0);
        uint2 yv = *(const uint2*)(y   + roff + i * 128 + c0);
        float2 a0 = __half22float2(*(__half2*)&rv.x);
        float2 a1 = __half22float2(*(__half2*)&rv.y);
        float2 f0 = __half22float2(*(__half2*)&yv.x);
        float2 f1 = __half22float2(*(__half2*)&yv.y);
        v[i*4+0] = a0.x + f0.x; v[i*4+1] = a0.y + f0.y;
        v[i*4+2] = a1.x + f1.x; v[i*4+3] = a1.y + f1.y;
    }
    float sum = 0.f, sq = 0.f;
#pragma unroll
    for (int k = 0; k < 16; k++) { sum += v[k]; sq += v[k] * v[k]; }
#pragma unroll
    for (int ofs = 16; ofs > 0; ofs >>= 1) {
        sum += __shfl_xor_sync(0xffffffffu, sum, ofs);
        sq  += __shfl_xor_sync(0xffffffffu, sq, ofs);
    }
    float mu   = sum * (1.0f / 512.0f);
    float var  = sq * (1.0f / 512.0f) - mu * mu;
    float rstd = rsqrtf(var + 1e-5f);

#pragma unroll
    for (int i = 0; i < 4; i++) {
        float4 g  = *(const float4*)(gam + i * 128 + c0);
        float4 be = *(const float4*)(bet + i * 128 + c0);
        float o0 = (v[i*4+0] - mu) * rstd * g.x + be.x;
        float o1 = (v[i*4+1] - mu) * rstd * g.y + be.y;
        float o2 = (v[i*4+2] - mu) * rstd * g.z + be.z;
        float o3 = (v[i*4+3] - mu) * rstd * g.w + be.w;
        uint2 w; w.x = pack2(o0, o1); w.y = pack2(o2, o3);
        *(uint2*)(out16 + roff + i * 128 + c0) = w;
    }
}

__global__ void add_ln2_kernel(
    const __half* __restrict__ res, const __half* __restrict__ y,
    const float* __restrict__ gam, const float* __restrict__ bet,
    float* __restrict__ out32)
{
    const int lane = threadIdx.x & 31;
    const int row  = blockIdx.x * 8 + (threadIdx.x >> 5);
    const size_t roff = (size_t)row * DMODEL;
    const int c0 = lane * 4;

    float v[16];
#pragma unroll
    for (int i = 0; i < 4; i++) {
        uint2 rv = *(const uint2*)(res + roff + i * 128 + c0);
        uint2 yv = *(const uint2*)(y   + roff + i * 128 + c0);
        float2 a0 = __half22float2(*(__half2*)&rv.x);
        float2 a1 = __half22float2(*(__half2*)&rv.y);
        float2 f0 = __half22float2(*(__half2*)&yv.x);
        float2 f1 = __half22float2(*(__half2*)&yv.y);
        v[i*4+0] = a0.x + f0.x; v[i*4+1] = a0.y + f0.y;
        v[i*4+2] = a1.x + f1.x; v[i*4+3] = a1.y + f1.y;
    }
    float sum = 0.f, sq = 0.f;
#pragma unroll
    for (int k = 0; k < 16; k++) { sum += v[k]; sq += v[k] * v[k]; }
#pragma unroll
    for (int ofs = 16; ofs > 0; ofs >>= 1) {
        sum += __shfl_xor_sync(0xffffffffu, sum, ofs);
        sq  += __shfl_xor_sync(0xffffffffu, sq, ofs);
    }
    float mu   = sum * (1.0f / 512.0f);
    float var  = sq * (1.0f / 512.0f) - mu * mu;
    float rstd = rsqrtf(var + 1e-5f);

#pragma unroll
    for (int i = 0; i < 4; i++) {
        float4 g  = *(const float4*)(gam + i * 128 + c0);
        float4 be = *(const float4*)(bet + i * 128 + c0);
        float4 w;
        w.x = (v[i*4+0] - mu) * rstd * g.x + be.x;
        w.y = (v[i*4+1] - mu) * rstd * g.y + be.y;
        w.z = (v[i*4+2] - mu) * rstd * g.z + be.z;
        w.w = (v[i*4+3] - mu) * rstd * g.w + be.w;
        *(float4*)(out32 + roff + i * 128 + c0) = w;
    }
}

// ---------------- launch ----------------
extern "C" void kernel_launch(void* const* d_in, const int* in_sizes, int n_in,
                              void* d_out, int out_size)
{
    const float* x      = (const float*)d_in[0];
    const float* w_qkv  = (const float*)d_in[1];
    const float* b_qkv  = (const float*)d_in[2];
    const float* w_out  = (const float*)d_in[3];
    const float* b_out  = (const float*)d_in[4];
    const float* w_l1   = (const float*)d_in[5];
    const float* b_l1   = (const float*)d_in[6];
    const float* w_l2   = (const float*)d_in[7];
    const float* b_l2   = (const float*)d_in[8];
    const float* ln1_g  = (const float*)d_in[9];
    const float* ln1_b  = (const float*)d_in[10];
    const float* ln2_g  = (const float*)d_in[11];
    const float* ln2_b  = (const float*)d_in[12];
    float* out = (float*)d_out;

    __half *xh, *qkv, *ctx, *hh, *ff, *t16, *w1, *w2, *w3, *w4;
    cudaGetSymbolAddress((void**)&xh,  g_xh);
    cudaGetSymbolAddress((void**)&qkv, g_qkv);
    cudaGetSymbolAddress((void**)&ctx, g_ctx);
    cudaGetSymbolAddress((void**)&hh,  g_hh);
    cudaGetSymbolAddress((void**)&ff,  g_ff);
    cudaGetSymbolAddress((void**)&t16, g_t16);
    cudaGetSymbolAddress((void**)&w1,  g_w1);
    cudaGetSymbolAddress((void**)&w2,  g_w2);
    cudaGetSymbolAddress((void**)&w3,  g_w3);
    cudaGetSymbolAddress((void**)&w4,  g_w4);

    const int attn_smem = ATTN_SMEM_HALVES * 2;   // 110592 B
    cudaFuncSetAttribute(attn_kernel, cudaFuncAttributeMaxDynamicSharedMemorySize, attn_smem);
    cudaFuncSetAttribute(gemm_kernel<0>, cudaFuncAttributeMaxDynamicSharedMemorySize, GSMEM);
    cudaFuncSetAttribute(gemm_kernel<2>, cudaFuncAttributeMaxDynamicSharedMemorySize, GSMEM);

    // converts (x + all weights, one launch)
    convall_kernel<<<(67108864 + 2097152) / 1024, 256>>>(
        x, w_qkv, w_out, w_l1, w_l2, xh, w1, w2, w3, w4);

    // 1) qkv = x @ in_proj_w^T + b
    gemm_kernel<0><<<dim3(TD / 128, N_TOK / 128), 256, GSMEM>>>(xh, w1, b_qkv, qkv, N_TOK, TD, DMODEL);

    // 2) attention
    attn_kernel<<<(N_TOK / SBLK) * NHEADS, 256, attn_smem>>>(qkv, ctx);

    // 3) attn_out = ctx @ out_w^T + b (fp16)
    gemm_kernel<0><<<dim3(DMODEL / 128, N_TOK / 128), 256, GSMEM>>>(ctx, w2, b_out, t16, N_TOK, DMODEL, DMODEL);

    // 4) hh = LN1(xh + attn_out)
    add_ln1_kernel<<<N_TOK / 8, 256>>>(xh, t16, ln1_g, ln1_b, hh);

    // 5) ff = gelu(hh @ lin1_w^T + b)
    gemm_kernel<2><<<dim3(DFFN / 128, N_TOK / 128), 256, GSMEM>>>(hh, w3, b_l1, ff, N_TOK, DFFN, DMODEL);

    // 6) f2 = ff @ lin2_w^T + b (fp16)
    gemm_kernel<0><<<dim3(DMODEL / 128, N_TOK / 128), 256, GSMEM>>>(ff, w4, b_l2, t16, N_TOK, DMODEL, DFFN);

    // 7) out = LN2(hh + f2)
    add_ln2_kernel<<<N_TOK / 8, 256>>>(hh, t16, ln2_g, ln2_b, out);
}

// round 17
// speedup vs baseline: 1.0128x; 1.0071x over previous
#include <cuda_runtime.h>
#include <cuda_fp16.h>
#include <cstdint>
#include <cstddef>

// ---------------- problem constants ----------------
#define N_TOK  131072
#define DMODEL 512
#define NHEADS 8
#define HDIM   64
#define SBLK   256
#define TD     1536   // 3*DMODEL
#define DFFN   1024

// ---------------- device scratch ----------------
__device__ __half g_xh  [(size_t)N_TOK * DMODEL];
__device__ __half g_qkv [(size_t)N_TOK * TD];
__device__ __half g_ctx [(size_t)N_TOK * DMODEL];
__device__ __half g_hh  [(size_t)N_TOK * DMODEL];
__device__ __half g_ff  [(size_t)N_TOK * DFFN];
__device__ __half g_t16 [(size_t)N_TOK * DMODEL];
__device__ __half g_w1  [TD     * DMODEL];
__device__ __half g_w2  [DMODEL * DMODEL];
__device__ __half g_w3  [DFFN   * DMODEL];
__device__ __half g_w4  [DMODEL * DFFN];

// ---------------- helpers ----------------
__device__ __forceinline__ uint32_t pack2(float a, float b) {
    __half2 h = __floats2half2_rn(a, b);
    return *reinterpret_cast<uint32_t*>(&h);
}
__device__ __forceinline__ void mma16816(float* c, const uint32_t* a, uint32_t b0, uint32_t b1) {
    asm volatile(
        "mma.sync.aligned.m16n8k16.row.col.f32.f16.f16.f32 "
        "{%0,%1,%2,%3}, {%4,%5,%6,%7}, {%8,%9}, {%0,%1,%2,%3};\n"
        : "+f"(c[0]), "+f"(c[1]), "+f"(c[2]), "+f"(c[3])
        : "r"(a[0]), "r"(a[1]), "r"(a[2]), "r"(a[3]), "r"(b0), "r"(b1));
}
__device__ __forceinline__ void ldsm4(uint32_t* r, uint32_t addr) {
    asm volatile("ldmatrix.sync.aligned.m8n8.x4.shared.b16 {%0,%1,%2,%3}, [%4];"
        : "=r"(r[0]), "=r"(r[1]), "=r"(r[2]), "=r"(r[3]) : "r"(addr));
}
__device__ __forceinline__ void ldsm4t(uint32_t* r, uint32_t addr) {
    asm volatile("ldmatrix.sync.aligned.m8n8.x4.trans.shared.b16 {%0,%1,%2,%3}, [%4];"
        : "=r"(r[0]), "=r"(r[1]), "=r"(r[2]), "=r"(r[3]) : "r"(addr));
}
__device__ __forceinline__ void cp16(uint32_t dst, const void* src) {
    asm volatile("cp.async.cg.shared.global [%0], [%1], 16;" :: "r"(dst), "l"(src));
}
__device__ __forceinline__ float gelu_exact(float v) {
    return 0.5f * v * (1.0f + erff(v * 0.7071067811865476f));
}
// exp(x * 0.125) with both constants folded: 0.125 * log2(e)
#define EXP8(x) exp2f((x) * 0.180336880111f)

// ---------------- fp32 -> fp16 converts: x + all 4 weights, one launch ----------------
__global__ void convall_kernel(const float* __restrict__ x,
                               const float* __restrict__ wq, const float* __restrict__ wo,
                               const float* __restrict__ wa, const float* __restrict__ wb,
                               __half* __restrict__ dx,
                               __half* __restrict__ d1, __half* __restrict__ d2,
                               __half* __restrict__ d3, __half* __restrict__ d4) {
    size_t i = ((size_t)blockIdx.x * blockDim.x + threadIdx.x) * 4;
    const float* src; __half* dst; size_t off;
    if      (i < 67108864)             { src = x;  dst = dx; off = i; }
    else if (i < 67108864 + 786432)    { src = wq; dst = d1; off = i - 67108864; }
    else if (i < 67108864 + 1048576)   { src = wo; dst = d2; off = i - 67108864 - 786432; }
    else if (i < 67108864 + 1572864)   { src = wa; dst = d3; off = i - 67108864 - 1048576; }
    else                               { src = wb; dst = d4; off = i - 67108864 - 1572864; }
    float4 v = *(const float4*)(src + off);
    __half2* o = (__half2*)(dst + off);
    o[0] = __floats2half2_rn(v.x, v.y);
    o[1] = __floats2half2_rn(v.z, v.w);
}

// ---------------- pipelined GEMM: kstep rotation + fragment double buffering (R16) ----------------
#define GS      3
#define GSTG_B  36864
#define GSMEM   (GS * GSTG_B)

template<int EPI>
__global__ __launch_bounds__(256, 2) void gemm_kernel(
    const __half* __restrict__ A, const __half* __restrict__ B,
    const float* __restrict__ bias, __half* __restrict__ Cout,
    int M, int Nn, int K)
{
    extern __shared__ __half gsm[];
    const uint32_t smem_u = (uint32_t)__cvta_generic_to_shared(gsm);

    const int tid  = threadIdx.x;
    const int lane = tid & 31, warp = tid >> 5;
    const int wm = warp & 3;
    const int wn = warp >> 2;
    const int lr = lane >> 2, lc = lane & 3;
    const int bm = blockIdx.y * 128, bn = blockIdx.x * 128;
    const int krot = warp & 3;

    float acc[2][8][4];
#pragma unroll
    for (int mi = 0; mi < 2; mi++)
#pragma unroll
        for (int nj = 0; nj < 8; nj++)
#pragma unroll
            for (int e = 0; e < 4; e++) acc[mi][nj][e] = 0.0f;

    const int r0 = tid >> 3;
    const int cc = tid & 7;
    const __half* Ag = A + (size_t)(bm + r0) * K + cc * 8;
    const __half* Bg = B + (size_t)(bn + r0) * K + cc * 8;
    const uint32_t stA = smem_u + r0 * 144 + cc * 16;
    const uint32_t stB = stA + 18432;

    const uint32_t aBase = smem_u +
        (((wm * 32 + (lane & 15)) * 72 + ((lane >> 4) << 3)) << 1);
    const uint32_t bBase = smem_u + 18432 +
        (((wn * 64 + ((lane & 16) >> 1) + (lane & 7)) * 72 + (lane & 8)) << 1);

    const int niter = K >> 6;

#define LOAD_STAGE(s, k0) do {                                    \
    const uint32_t off = (uint32_t)(s) * GSTG_B;                  \
    _Pragma("unroll")                                             \
    for (int j = 0; j < 4; j++)                                   \
        cp16(stA + off + j * 4608, Ag + (k0) + (size_t)(32 * j) * K); \
    _Pragma("unroll")                                             \
    for (int j = 0; j < 4; j++)                                   \
        cp16(stB + off + j * 4608, Bg + (k0) + (size_t)(32 * j) * K); \
    } while (0)

    LOAD_STAGE(0, 0);  asm volatile("cp.async.commit_group;");
    LOAD_STAGE(1, 64); asm volatile("cp.async.commit_group;");

    for (int d = 0; d < niter; d++) {
        asm volatile("cp.async.wait_group 1;");
        __syncthreads();
        if (d + 2 < niter) LOAD_STAGE((d + 2) % GS, (d + 2) << 6);
        asm volatile("cp.async.commit_group;");

        const uint32_t soff = (uint32_t)(d % GS) * GSTG_B;

        uint32_t af[2][2][4];   // [buf][mi][frag] - A, double-buffered across ksteps
        uint32_t bf[2][4];      // [buf][frag]     - B, double-buffered across njp

        ldsm4(af[0][0], aBase + soff + krot * 32);
        ldsm4(af[0][1], aBase + soff + krot * 32 + 16 * 144);
        ldsm4(bf[0],    bBase + soff + krot * 32);

#pragma unroll
        for (int k0 = 0; k0 < 4; k0++) {
            const int ks  = (k0 + krot) & 3;
            const int ksn = (k0 + 1 + krot) & 3;
            const int ab  = k0 & 1;
            if (k0 < 3) {
                ldsm4(af[ab ^ 1][0], aBase + soff + ksn * 32);
                ldsm4(af[ab ^ 1][1], aBase + soff + ksn * 32 + 16 * 144);
            }
#pragma unroll
            for (int njp = 0; njp < 4; njp++) {
                const int bb = njp & 1;
                if (njp < 3)
                    ldsm4(bf[bb ^ 1], bBase + soff + ks * 32 + (njp + 1) * 16 * 144);
                else if (k0 < 3)
                    ldsm4(bf[bb ^ 1], bBase + soff + ksn * 32);
                mma16816(acc[0][2 * njp],     af[ab][0], bf[bb][0], bf[bb][1]);
                mma16816(acc[1][2 * njp],     af[ab][1], bf[bb][0], bf[bb][1]);
                mma16816(acc[0][2 * njp + 1], af[ab][0], bf[bb][2], bf[bb][3]);
                mma16816(acc[1][2 * njp + 1], af[ab][1], bf[bb][2], bf[bb][3]);
            }
        }
    }
#undef LOAD_STAGE

    __syncthreads();

#pragma unroll
    for (int mi = 0; mi < 2; mi++) {
#pragma unroll
        for (int nj = 0; nj < 8; nj++) {
            int gr = bm + wm * 32 + mi * 16 + lr;
            int gc = bn + wn * 64 + nj * 8 + lc * 2;
            float bb0 = bias[gc], bb1 = bias[gc + 1];
            float v00 = acc[mi][nj][0] + bb0;
            float v01 = acc[mi][nj][1] + bb1;
            float v10 = acc[mi][nj][2] + bb0;
            float v11 = acc[mi][nj][3] + bb1;
            if (EPI == 2) {
                v00 = gelu_exact(v00); v01 = gelu_exact(v01);
                v10 = gelu_exact(v10); v11 = gelu_exact(v11);
            }
            *(uint32_t*)&Cout[(size_t)gr * Nn + gc]       = pack2(v00, v01);
            *(uint32_t*)&Cout[(size_t)(gr + 8) * Nn + gc] = pack2(v10, v11);
        }
    }
}

// ---------------- attention: Q/K/V staged in smem; ldsm everywhere (R12-proven) ----------------
#define ATTN_SMEM_HALVES (3 * 256 * 72)

__global__ __launch_bounds__(256, 2) void attn_kernel(
    const __half* __restrict__ qkv, __half* __restrict__ ctx)
{
    extern __shared__ __half sm[];
    __half* sQ = sm;                   // [256][72] token-major
    __half* sK = sm + 256 * 72;
    __half* sV = sm + 2 * 256 * 72;

    const int tid  = threadIdx.x;
    const int lane = tid & 31, warp = tid >> 5;
    const int lr = lane >> 2, lc = lane & 3;
    const int b = blockIdx.x >> 3, h = blockIdx.x & 7;
    const __half* base = qkv + (size_t)b * SBLK * TD;

    const uint32_t sQ_u = (uint32_t)__cvta_generic_to_shared(sQ);
    const uint32_t sK_u = (uint32_t)__cvta_generic_to_shared(sK);
    const uint32_t sV_u = (uint32_t)__cvta_generic_to_shared(sV);

    for (int idx = tid; idx < 256 * 16; idx += 256) {
        int t = idx >> 4, d4 = (idx & 15) * 4;
        const __half* p = base + (size_t)t * TD + h * HDIM + d4;
        uint2 vq = *(const uint2*)(p);
        uint2 vk = *(const uint2*)(p + DMODEL);
        uint2 vv = *(const uint2*)(p + 2 * DMODEL);
        *(uint2*)&sQ[t * 72 + d4] = vq;
        *(uint2*)&sK[t * 72 + d4] = vk;
        *(uint2*)&sV[t * 72 + d4] = vv;
    }
    __syncthreads();

    const uint32_t qBase = sQ_u +
        (((lane & 15) * 72 + ((lane >> 4) << 3)) << 1);
    const uint32_t kBase = sK_u +
        (((((lane & 16) >> 1) + (lane & 7)) * 72 + (lane & 8)) << 1);
    const uint32_t vBase = sV_u +
        ((((lane & 8) + (lane & 7)) * 72 + ((lane & 16) >> 1)) << 1);

#pragma unroll 1
    for (int mh = 0; mh < 2; mh++) {
        const int mbase = mh * 128 + warp * 16;

        uint32_t qf[4][4];
#pragma unroll
        for (int ks = 0; ks < 4; ks++)
            ldsm4(qf[ks], qBase + mbase * 144 + ks * 32);

        float o[8][4];
#pragma unroll
        for (int dj = 0; dj < 8; dj++)
#pragma unroll
            for (int e = 0; e < 4; e++) o[dj][e] = 0.0f;
        float rs0 = 0.f, rs1 = 0.f;

#pragma unroll
        for (int kt = 0; kt < 4; kt++) {
            float s[8][4];
#pragma unroll
            for (int nj = 0; nj < 8; nj++)
#pragma unroll
                for (int e = 0; e < 4; e++) s[nj][e] = 0.0f;

#pragma unroll
            for (int ks = 0; ks < 4; ks++) {
#pragma unroll
                for (int njp = 0; njp < 4; njp++) {
                    uint32_t bf[4];
                    ldsm4(bf, kBase + (((kt * 64 + njp * 16) * 72 + ks * 16) << 1));
                    mma16816(s[2 * njp],     qf[ks], bf[0], bf[1]);
                    mma16816(s[2 * njp + 1], qf[ks], bf[2], bf[3]);
                }
            }

            uint32_t pa[4][4];
#pragma unroll
            for (int nj = 0; nj < 8; nj++) {
                float e0 = EXP8(s[nj][0]);
                float e1 = EXP8(s[nj][1]);
                float e2 = EXP8(s[nj][2]);
                float e3 = EXP8(s[nj][3]);
                rs0 += e0 + e1;
                rs1 += e2 + e3;
                pa[nj >> 1][(nj & 1) * 2 + 0] = pack2(e0, e1);
                pa[nj >> 1][(nj & 1) * 2 + 1] = pack2(e2, e3);
            }

#pragma unroll
            for (int ks2 = 0; ks2 < 4; ks2++) {
#pragma unroll
                for (int djp = 0; djp < 4; djp++) {
                    uint32_t bf[4];
                    ldsm4t(bf, vBase + (((kt * 64 + ks2 * 16) * 72 + djp * 16) << 1));
                    mma16816(o[2 * djp],     pa[ks2], bf[0], bf[1]);
                    mma16816(o[2 * djp + 1], pa[ks2], bf[2], bf[3]);
                }
            }
        }

        rs0 += __shfl_xor_sync(0xffffffffu, rs0, 1);
        rs0 += __shfl_xor_sync(0xffffffffu, rs0, 2);
        rs1 += __shfl_xor_sync(0xffffffffu, rs1, 1);
        rs1 += __shfl_xor_sync(0xffffffffu, rs1, 2);

        const float i0 = 1.0f / rs0;
        const float i1 = 1.0f / rs1;
#pragma unroll
        for (int dj = 0; dj < 8; dj++) {
            int gr = b * SBLK + mbase + lr;
            int gc = h * HDIM + dj * 8 + lc * 2;
            *(uint32_t*)&ctx[(size_t)gr * DMODEL + gc] =
                pack2(o[dj][0] * i0, o[dj][1] * i0);
            *(uint32_t*)&ctx[(size_t)(gr + 8) * DMODEL + gc] =
                pack2(o[dj][2] * i1, o[dj][3] * i1);
        }
    }
}

// ---------------- residual add + LayerNorm: warp per row ----------------
__global__ void add_ln1_kernel(
    const __half* __restrict__ res, const __half* __restrict__ y,
    const float* __restrict__ gam, const float* __restrict__ bet,
    __half* __restrict__ out16)
{
    const int lane = threadIdx.x & 31;
    const int row  = blockIdx.x * 8 + (threadIdx.x >> 5);
    const size_t roff = (size_t)row * DMODEL;
    const int c0 = lane * 4;

    float v[16];
#pragma unroll
    for (int i = 0; i < 4; i++) {
        uint2 rv = *(const uint2*)(res + roff + i * 128 + c0);
        uint2 yv = *(const uint2*)(y   + roff + i * 128 + c0);
        float2 a0 = __half22float2(*(__half2*)&rv.x);
        float2 a1 = __half22float2(*(__half2*)&rv.y);
        float2 f0 = __half22float2(*(__half2*)&yv.x);
        float2 f1 = __half22float2(*(__half2*)&yv.y);
        v[i*4+0] = a0.x + f0.x; v[i*4+1] = a0.y + f0.y;
        v[i*4+2] = a1.x + f1.x; v[i*4+3] = a1.y + f1.y;
    }
    float sum = 0.f, sq = 0.f;
#pragma unroll
    for (int k = 0; k < 16; k++) { sum += v[k]; sq += v[k] * v[k]; }
#pragma unroll
    for (int ofs = 16; ofs > 0; ofs >>= 1) {
        sum += __shfl_xor_sync(0xffffffffu, sum, ofs);
        sq  += __shfl_xor_sync(0xffffffffu, sq, ofs);
    }
    float mu   = sum * (1.0f / 512.0f);
    float var  = sq * (1.0f / 512.0f) - mu * mu;
    float rstd = rsqrtf(var + 1e-5f);

#pragma unroll
    for (int i = 0; i < 4; i++) {
        float4 g  = __ldg((const float4*)(gam + i * 128 + c0));
        float4 be = __ldg((const float4*)(bet + i * 128 + c0));
        float o0 = (v[i*4+0] - mu) * rstd * g.x + be.x;
        float o1 = (v[i*4+1] - mu) * rstd * g.y + be.y;
        float o2 = (v[i*4+2] - mu) * rstd * g.z + be.z;
        float o3 = (v[i*4+3] - mu) * rstd * g.w + be.w;
        uint2 w; w.x = pack2(o0, o1); w.y = pack2(o2, o3);
        *(uint2*)(out16 + roff + i * 128 + c0) = w;
    }
}

__global__ void add_ln2_kernel(
    const __half* __restrict__ res, const __half* __restrict__ y,
    const float* __restrict__ gam, const float* __restrict__ bet,
    float* __restrict__ out32)
{
    const int lane = threadIdx.x & 31;
    const int row  = blockIdx.x * 8 + (threadIdx.x >> 5);
    const size_t roff = (size_t)row * DMODEL;
    const int c0 = lane * 4;

    float v[16];
#pragma unroll
    for (int i = 0; i < 4; i++) {
        uint2 rv = *(const uint2*)(res + roff + i * 128 + c0);
        uint2 yv = *(const uint2*)(y   + roff + i * 128 + c0);
        float2 a0 = __half22float2(*(__half2*)&rv.x);
        float2 a1 = __half22float2(*(__half2*)&rv.y);
        float2 f0 = __half22float2(*(__half2*)&yv.x);
        float2 f1 = __half22float2(*(__half2*)&yv.y);
        v[i*4+0] = a0.x + f0.x; v[i*4+1] = a0.y + f0.y;
        v[i*4+2] = a1.x + f1.x; v[i*4+3] = a1.y + f1.y;
    }
    float sum = 0.f, sq = 0.f;
#pragma unroll
    for (int k = 0; k < 16; k++) { sum += v[k]; sq += v[k] * v[k]; }
#pragma unroll
    for (int ofs = 16; ofs > 0; ofs >>= 1) {
        sum += __shfl_xor_sync(0xffffffffu, sum, ofs);
        sq  += __shfl_xor_sync(0xffffffffu, sq, ofs);
    }
    float mu   = sum * (1.0f / 512.0f);
    float var  = sq * (1.0f / 512.0f) - mu * mu;
    float rstd = rsqrtf(var + 1e-5f);

#pragma unroll
    for (int i = 0; i < 4; i++) {
        float4 g  = __ldg((const float4*)(gam + i * 128 + c0));
        float4 be = __ldg((const float4*)(bet + i * 128 + c0));
        float4 w;
        w.x = (v[i*4+0] - mu) * rstd * g.x + be.x;
        w.y = (v[i*4+1] - mu) * rstd * g.y + be.y;
        w.z = (v[i*4+2] - mu) * rstd * g.z + be.z;
        w.w = (v[i*4+3] - mu) * rstd * g.w + be.w;
        *(float4*)(out32 + roff + i * 128 + c0) = w;
    }
}

// ---------------- launch ----------------
extern "C" void kernel_launch(void* const* d_in, const int* in_sizes, int n_in,
                              void* d_out, int out_size)
{
    const float* x      = (const float*)d_in[0];
    const float* w_qkv  = (const float*)d_in[1];
    const float* b_qkv  = (const float*)d_in[2];
    const float* w_out  = (const float*)d_in[3];
    const float* b_out  = (const float*)d_in[4];
    const float* w_l1   = (const float*)d_in[5];
    const float* b_l1   = (const float*)d_in[6];
    const float* w_l2   = (const float*)d_in[7];
    const float* b_l2   = (const float*)d_in[8];
    const float* ln1_g  = (const float*)d_in[9];
    const float* ln1_b  = (const float*)d_in[10];
    const float* ln2_g  = (const float*)d_in[11];
    const float* ln2_b  = (const float*)d_in[12];
    float* out = (float*)d_out;

    __half *xh, *qkv, *ctx, *hh, *ff, *t16, *w1, *w2, *w3, *w4;
    cudaGetSymbolAddress((void**)&xh,  g_xh);
    cudaGetSymbolAddress((void**)&qkv, g_qkv);
    cudaGetSymbolAddress((void**)&ctx, g_ctx);
    cudaGetSymbolAddress((void**)&hh,  g_hh);
    cudaGetSymbolAddress((void**)&ff,  g_ff);
    cudaGetSymbolAddress((void**)&t16, g_t16);
    cudaGetSymbolAddress((void**)&w1,  g_w1);
    cudaGetSymbolAddress((void**)&w2,  g_w2);
    cudaGetSymbolAddress((void**)&w3,  g_w3);
    cudaGetSymbolAddress((void**)&w4,  g_w4);

    const int attn_smem = ATTN_SMEM_HALVES * 2;   // 110592 B
    cudaFuncSetAttribute(attn_kernel, cudaFuncAttributeMaxDynamicSharedMemorySize, attn_smem);
    cudaFuncSetAttribute(gemm_kernel<0>, cudaFuncAttributeMaxDynamicSharedMemorySize, GSMEM);
    cudaFuncSetAttribute(gemm_kernel<2>, cudaFuncAttributeMaxDynamicSharedMemorySize, GSMEM);

    // converts (x + all weights, one launch)
    convall_kernel<<<(67108864 + 2097152) / 1024, 256>>>(
        x, w_qkv, w_out, w_l1, w_l2, xh, w1, w2, w3, w4);

    // 1) qkv = x @ in_proj_w^T + b
    gemm_kernel<0><<<dim3(TD / 128, N_TOK / 128), 256, GSMEM>>>(xh, w1, b_qkv, qkv, N_TOK, TD, DMODEL);

    // 2) attention
    attn_kernel<<<(N_TOK / SBLK) * NHEADS, 256, attn_smem>>>(qkv, ctx);

    // 3) attn_out = ctx @ out_w^T + b (fp16)
    gemm_kernel<0><<<dim3(DMODEL / 128, N_TOK / 128), 256, GSMEM>>>(ctx, w2, b_out, t16, N_TOK, DMODEL, DMODEL);

    // 4) hh = LN1(xh + attn_out)
    add_ln1_kernel<<<N_TOK / 8, 256>>>(xh, t16, ln1_g, ln1_b, hh);

    // 5) ff = gelu(hh @ lin1_w^T + b)
    gemm_kernel<2><<<dim3(DFFN / 128, N_TOK / 128), 256, GSMEM>>>(hh, w3, b_l1, ff, N_TOK, DFFN, DMODEL);

    // 6) f2 = ff @ lin2_w^T + b (fp16)
    gemm_kernel<0><<<dim3(DMODEL / 128, N_TOK / 128), 256, GSMEM>>>(ff, w4, b_l2, t16, N_TOK, DMODEL, DFFN);

    // 7) out = LN2(hh + f2)
    add_ln2_kernel<<<N_TOK / 8, 256>>>(hh, t16, ln2_g, ln2_b, out);
}